// round 1
// baseline (speedup 1.0000x reference)
#include <cuda_runtime.h>

#define EMBED 1024
#define NHEADS 16
#define HDIM 64
#define SEQ 2048
#define NCLS 1000

// Scratch (allocation-free rule: __device__ globals)
__device__ float g_P[4096u * 1024u];
__device__ float g_V[4096u * 1024u];
__device__ float g_G[32 * 64 * 64];

// C[M,N] = A[M,K] @ B[N,K]^T + bias[N]
// Both A and B are K-contiguous (row-major). 128x128x8 tile, 256 threads, 8x8 per thread.
__global__ __launch_bounds__(256) void gemm_nt_bias(
    const float* __restrict__ A, const float* __restrict__ B,
    const float* __restrict__ bias, float* __restrict__ C,
    int M, int N, int K)
{
    const int BM = 128, BN = 128, BK = 8;
    __shared__ float As[BK][BM];
    __shared__ float Bs[BK][BN];

    int tid = threadIdx.x;
    int m0 = blockIdx.y * BM;
    int n0 = blockIdx.x * BN;

    int loadRow = tid >> 1;          // 0..127
    int loadK   = (tid & 1) * 4;     // 0 or 4
    const float* Aptr = A + (size_t)(m0 + loadRow) * K + loadK;
    const float* Bptr = B + (size_t)(n0 + loadRow) * K + loadK;
    bool bValid = (n0 + loadRow) < N;

    int tx = tid & 15;   // 16 cols of threads
    int ty = tid >> 4;   // 16 rows of threads

    float acc[8][8];
#pragma unroll
    for (int i = 0; i < 8; i++)
#pragma unroll
        for (int j = 0; j < 8; j++) acc[i][j] = 0.f;

    for (int k0 = 0; k0 < K; k0 += BK) {
        float4 a4 = *(const float4*)(Aptr + k0);
        float4 b4 = bValid ? *(const float4*)(Bptr + k0)
                           : make_float4(0.f, 0.f, 0.f, 0.f);
        __syncthreads();
        As[loadK + 0][loadRow] = a4.x;
        As[loadK + 1][loadRow] = a4.y;
        As[loadK + 2][loadRow] = a4.z;
        As[loadK + 3][loadRow] = a4.w;
        Bs[loadK + 0][loadRow] = b4.x;
        Bs[loadK + 1][loadRow] = b4.y;
        Bs[loadK + 2][loadRow] = b4.z;
        Bs[loadK + 3][loadRow] = b4.w;
        __syncthreads();

#pragma unroll
        for (int k = 0; k < BK; k++) {
            float4 a0 = *(const float4*)&As[k][ty * 8];
            float4 a1 = *(const float4*)&As[k][ty * 8 + 4];
            float4 b0 = *(const float4*)&Bs[k][tx * 8];
            float4 b1 = *(const float4*)&Bs[k][tx * 8 + 4];
            float af[8] = {a0.x, a0.y, a0.z, a0.w, a1.x, a1.y, a1.z, a1.w};
            float bf[8] = {b0.x, b0.y, b0.z, b0.w, b1.x, b1.y, b1.z, b1.w};
#pragma unroll
            for (int i = 0; i < 8; i++)
#pragma unroll
                for (int j = 0; j < 8; j++)
                    acc[i][j] += af[i] * bf[j];
        }
    }

#pragma unroll
    for (int i = 0; i < 8; i++) {
        int m = m0 + ty * 8 + i;
#pragma unroll
        for (int j = 0; j < 8; j++) {
            int n = n0 + tx * 8 + j;
            if (n < N) C[(size_t)m * N + n] = acc[i][j] + bias[n];
        }
    }
}

// G[b,h] = scale * P_h^T @ P_h, where P_h = P[b, :, h*64 : h*64+64]  (64x64 out, K=SEQ)
__global__ __launch_bounds__(256) void head_gram(
    const float* __restrict__ P, float* __restrict__ G, float scale)
{
    int bh = blockIdx.x;
    int b = bh >> 4;
    int h = bh & 15;
    const float* Pb = P + (size_t)b * SEQ * EMBED + h * HDIM;

    __shared__ float Ps[64][65];
    int tid = threadIdx.x;
    int j  = tid & 63;
    int i0 = (tid >> 6) << 4;   // 0,16,32,48

    float acc[16];
#pragma unroll
    for (int ii = 0; ii < 16; ii++) acc[ii] = 0.f;

    for (int s0 = 0; s0 < SEQ; s0 += 64) {
        __syncthreads();
#pragma unroll
        for (int v = 0; v < 4; v++) {
            int idx = tid + v * 256;       // 0..1023
            int r = idx >> 4;              // 0..63
            int c = (idx & 15) << 2;       // 0..60 step 4
            float4 p4 = *(const float4*)(Pb + (size_t)(s0 + r) * EMBED + c);
            Ps[r][c + 0] = p4.x; Ps[r][c + 1] = p4.y;
            Ps[r][c + 2] = p4.z; Ps[r][c + 3] = p4.w;
        }
        __syncthreads();
#pragma unroll 4
        for (int s = 0; s < 64; s++) {
            float bj = Ps[s][j];
#pragma unroll
            for (int ii = 0; ii < 16; ii++)
                acc[ii] += Ps[s][i0 + ii] * bj;
        }
    }

    float* Gh = G + (size_t)bh * HDIM * HDIM;
#pragma unroll
    for (int ii = 0; ii < 16; ii++)
        Gh[(i0 + ii) * HDIM + j] = acc[ii] * scale;
}

// V[r, h*64+j] = sum_k P[r, h*64+k] * G[b,h][k][j]   (64-row tiles)
__global__ __launch_bounds__(256) void apply_gram(
    const float* __restrict__ P, const float* __restrict__ G, float* __restrict__ V)
{
    int h  = blockIdx.y;
    int r0 = blockIdx.x * 64;
    int b  = r0 / SEQ;
    const float* Gh = G + (size_t)(b * NHEADS + h) * HDIM * HDIM;

    __shared__ float Gs[64][65];
    __shared__ float Ps[64][65];
    int tid = threadIdx.x;

#pragma unroll
    for (int v = 0; v < 4; v++) {
        int idx = tid + v * 256;
        int r = idx >> 4;
        int c = (idx & 15) << 2;
        float4 g4 = *(const float4*)(Gh + r * HDIM + c);
        Gs[r][c + 0] = g4.x; Gs[r][c + 1] = g4.y;
        Gs[r][c + 2] = g4.z; Gs[r][c + 3] = g4.w;
        float4 p4 = *(const float4*)(P + (size_t)(r0 + r) * EMBED + h * HDIM + c);
        Ps[r][c + 0] = p4.x; Ps[r][c + 1] = p4.y;
        Ps[r][c + 2] = p4.z; Ps[r][c + 3] = p4.w;
    }
    __syncthreads();

    int j  = tid & 63;
    int i0 = (tid >> 6) << 4;
    float acc[16];
#pragma unroll
    for (int ii = 0; ii < 16; ii++) acc[ii] = 0.f;

#pragma unroll 4
    for (int k = 0; k < 64; k++) {
        float g = Gs[k][j];
#pragma unroll
        for (int ii = 0; ii < 16; ii++)
            acc[ii] += Ps[i0 + ii][k] * g;
    }

#pragma unroll
    for (int ii = 0; ii < 16; ii++)
        V[(size_t)(r0 + i0 + ii) * EMBED + h * HDIM + j] = acc[ii];
}

extern "C" void kernel_launch(void* const* d_in, const int* in_sizes, int n_in,
                              void* d_out, int out_size)
{
    const float* x     = (const float*)d_in[0];
    const float* W_in  = (const float*)d_in[1];
    const float* b_in  = (const float*)d_in[2];
    const float* W_out = (const float*)d_in[3];
    const float* b_out = (const float*)d_in[4];
    float* out = (float*)d_out;

    int M = in_sizes[0] / EMBED;   // bs*seq = 4096

    float *P, *V, *G;
    cudaGetSymbolAddress((void**)&P, g_P);
    cudaGetSymbolAddress((void**)&V, g_V);
    cudaGetSymbolAddress((void**)&G, g_G);

    dim3 blk(256);

    // 1) P = X @ W_in^T + b_in
    gemm_nt_bias<<<dim3(EMBED / 128, M / 128), blk>>>(x, W_in, b_in, P, M, EMBED, EMBED);

    // 2) G[b,h] = scale * P_h^T P_h   (scale = 1/sqrt(1024) = 1/32 exactly)
    head_gram<<<dim3((M / SEQ) * NHEADS), blk>>>(P, G, 1.0f / 32.0f);

    // 3) V = P @ G per head
    apply_gram<<<dim3(M / 64, NHEADS), blk>>>(P, G, V);

    // 4) out = V @ W_out^T + b_out
    gemm_nt_bias<<<dim3((NCLS + 127) / 128, M / 128), blk>>>(V, W_out, b_out, out, M, NCLS, EMBED);
}

// round 2
// speedup vs baseline: 1.1784x; 1.1784x over previous
#include <cuda_runtime.h>

#define EMBED 1024
#define NHEADS 16
#define HDIM 64
#define SEQ 2048
#define NCLS 1000
#define GCHUNKS 8

// Scratch (allocation-free rule: __device__ globals)
__device__ float g_P[4096u * 1024u];
__device__ float g_V[4096u * 1024u];
__device__ float g_G[32 * 64 * 64];
__device__ float g_Gpart[GCHUNKS][32][64 * 64];

#define FMA2(acc, a, b) \
    asm("fma.rn.f32x2 %0, %1, %2, %0;" : "+l"(acc) : "l"(a), "l"(b))
#define SPLAT2(d, s) \
    asm("mov.b64 %0, {%1, %1};" : "=l"(d) : "r"(__float_as_uint(s)))
#define UNPACK2(lo, hi, v) \
    asm("mov.b64 {%0, %1}, %2;" : "=r"(lo), "=r"(hi) : "l"(v))

// C[M,N] = A[M,K] @ B[N,K]^T + bias[N]; K-contiguous A,B. 128x128x8 tile,
// 256 threads, 8x8 per thread computed as 8x4 packed f32x2.
__global__ __launch_bounds__(256, 2) void gemm_nt_bias(
    const float* __restrict__ A, const float* __restrict__ B,
    const float* __restrict__ bias, float* __restrict__ C,
    int M, int N, int K)
{
    const int BM = 128, BK = 8;
    __shared__ float As[BK][BM];
    __shared__ float Bs[BK][BM];

    int tid = threadIdx.x;
    int m0 = blockIdx.y * BM;
    int n0 = blockIdx.x * BM;

    int loadRow = tid >> 1;          // 0..127
    int loadK   = (tid & 1) * 4;     // 0 or 4
    const float* Aptr = A + (size_t)(m0 + loadRow) * K + loadK;
    const float* Bptr = B + (size_t)(n0 + loadRow) * K + loadK;
    bool bValid = (n0 + loadRow) < N;

    int tx = tid & 15;   // 16 thread-cols
    int ty = tid >> 4;   // 16 thread-rows

    unsigned long long acc[8][4];
#pragma unroll
    for (int i = 0; i < 8; i++)
#pragma unroll
        for (int j = 0; j < 4; j++) acc[i][j] = 0ull;

    // prefetch first tile
    float4 a4 = *(const float4*)(Aptr);
    float4 b4 = bValid ? *(const float4*)(Bptr) : make_float4(0.f, 0.f, 0.f, 0.f);

    for (int k0 = 0; k0 < K; k0 += BK) {
        As[loadK + 0][loadRow] = a4.x;
        As[loadK + 1][loadRow] = a4.y;
        As[loadK + 2][loadRow] = a4.z;
        As[loadK + 3][loadRow] = a4.w;
        Bs[loadK + 0][loadRow] = b4.x;
        Bs[loadK + 1][loadRow] = b4.y;
        Bs[loadK + 2][loadRow] = b4.z;
        Bs[loadK + 3][loadRow] = b4.w;
        __syncthreads();

        if (k0 + BK < K) {
            a4 = *(const float4*)(Aptr + k0 + BK);
            b4 = bValid ? *(const float4*)(Bptr + k0 + BK)
                        : make_float4(0.f, 0.f, 0.f, 0.f);
        }

#pragma unroll
        for (int k = 0; k < BK; k++) {
            float4 a0 = *(const float4*)&As[k][ty * 8];
            float4 a1 = *(const float4*)&As[k][ty * 8 + 4];
            ulonglong2 bb01 = *(const ulonglong2*)&Bs[k][tx * 8];
            ulonglong2 bb23 = *(const ulonglong2*)&Bs[k][tx * 8 + 4];
            unsigned long long bb[4] = {bb01.x, bb01.y, bb23.x, bb23.y};
            float af[8] = {a0.x, a0.y, a0.z, a0.w, a1.x, a1.y, a1.z, a1.w};
#pragma unroll
            for (int i = 0; i < 8; i++) {
                unsigned long long aa;
                SPLAT2(aa, af[i]);
#pragma unroll
                for (int j = 0; j < 4; j++)
                    FMA2(acc[i][j], aa, bb[j]);
            }
        }
        __syncthreads();
    }

#pragma unroll
    for (int i = 0; i < 8; i++) {
        int m = m0 + ty * 8 + i;
        float* Crow = C + (size_t)m * N;
#pragma unroll
        for (int j = 0; j < 4; j++) {
            int n = n0 + tx * 8 + j * 2;
            unsigned lo, hi;
            UNPACK2(lo, hi, acc[i][j]);
            if (n < N)     Crow[n]     = __uint_as_float(lo) + bias[n];
            if (n + 1 < N) Crow[n + 1] = __uint_as_float(hi) + bias[n + 1];
        }
    }
}

// Partial Gram: Gpart[chunk][bh] = P_h[chunk rows]^T @ P_h[chunk rows]
__global__ __launch_bounds__(256) void head_gram_part(
    const float* __restrict__ P, float* __restrict__ Gpart)
{
    int bh = blockIdx.x;
    int chunk = blockIdx.y;
    int b = bh >> 4;
    int h = bh & 15;
    const float* Pb = P + (size_t)b * SEQ * EMBED + h * HDIM;
    int sBeg = chunk * (SEQ / GCHUNKS);

    __shared__ float Ps[64][65];
    int tid = threadIdx.x;
    int j  = tid & 63;
    int i0 = (tid >> 6) << 4;   // 0,16,32,48

    float acc[16];
#pragma unroll
    for (int ii = 0; ii < 16; ii++) acc[ii] = 0.f;

    for (int s0 = sBeg; s0 < sBeg + SEQ / GCHUNKS; s0 += 64) {
        __syncthreads();
#pragma unroll
        for (int v = 0; v < 4; v++) {
            int idx = tid + v * 256;
            int r = idx >> 4;
            int c = (idx & 15) << 2;
            float4 p4 = *(const float4*)(Pb + (size_t)(s0 + r) * EMBED + c);
            Ps[r][c + 0] = p4.x; Ps[r][c + 1] = p4.y;
            Ps[r][c + 2] = p4.z; Ps[r][c + 3] = p4.w;
        }
        __syncthreads();
#pragma unroll 4
        for (int s = 0; s < 64; s++) {
            float bj = Ps[s][j];
#pragma unroll
            for (int ii = 0; ii < 16; ii++)
                acc[ii] += Ps[s][i0 + ii] * bj;
        }
    }

    float* Gp = Gpart + ((size_t)chunk * 32 + bh) * (HDIM * HDIM);
#pragma unroll
    for (int ii = 0; ii < 16; ii++)
        Gp[(i0 + ii) * HDIM + j] = acc[ii];
}

// G = scale * sum_chunks Gpart   (deterministic tree-free fixed-order sum)
__global__ void gram_reduce(const float* __restrict__ Gpart,
                            float* __restrict__ G, float scale)
{
    int idx = blockIdx.x * blockDim.x + threadIdx.x;  // over 32*4096
    if (idx >= 32 * HDIM * HDIM) return;
    float s = 0.f;
#pragma unroll
    for (int c = 0; c < GCHUNKS; c++)
        s += Gpart[(size_t)c * 32 * HDIM * HDIM + idx];
    G[idx] = s * scale;
}

// V[r, h*64+j] = sum_k P[r, h*64+k] * G[b,h][k][j]   (64-row tiles)
__global__ __launch_bounds__(256) void apply_gram(
    const float* __restrict__ P, const float* __restrict__ G, float* __restrict__ V)
{
    int h  = blockIdx.y;
    int r0 = blockIdx.x * 64;
    int b  = r0 / SEQ;
    const float* Gh = G + (size_t)(b * NHEADS + h) * HDIM * HDIM;

    __shared__ float Gs[64][65];
    __shared__ float Ps[64][65];
    int tid = threadIdx.x;

#pragma unroll
    for (int v = 0; v < 4; v++) {
        int idx = tid + v * 256;
        int r = idx >> 4;
        int c = (idx & 15) << 2;
        float4 g4 = *(const float4*)(Gh + r * HDIM + c);
        Gs[r][c + 0] = g4.x; Gs[r][c + 1] = g4.y;
        Gs[r][c + 2] = g4.z; Gs[r][c + 3] = g4.w;
        float4 p4 = *(const float4*)(P + (size_t)(r0 + r) * EMBED + h * HDIM + c);
        Ps[r][c + 0] = p4.x; Ps[r][c + 1] = p4.y;
        Ps[r][c + 2] = p4.z; Ps[r][c + 3] = p4.w;
    }
    __syncthreads();

    int j  = tid & 63;
    int i0 = (tid >> 6) << 4;
    float acc[16];
#pragma unroll
    for (int ii = 0; ii < 16; ii++) acc[ii] = 0.f;

#pragma unroll 4
    for (int k = 0; k < 64; k++) {
        float g = Gs[k][j];
#pragma unroll
        for (int ii = 0; ii < 16; ii++)
            acc[ii] += Ps[i0 + ii][k] * g;
    }

#pragma unroll
    for (int ii = 0; ii < 16; ii++)
        V[(size_t)(r0 + i0 + ii) * EMBED + h * HDIM + j] = acc[ii];
}

extern "C" void kernel_launch(void* const* d_in, const int* in_sizes, int n_in,
                              void* d_out, int out_size)
{
    const float* x     = (const float*)d_in[0];
    const float* W_in  = (const float*)d_in[1];
    const float* b_in  = (const float*)d_in[2];
    const float* W_out = (const float*)d_in[3];
    const float* b_out = (const float*)d_in[4];
    float* out = (float*)d_out;

    int M = in_sizes[0] / EMBED;   // bs*seq = 4096

    float *P, *V, *G, *Gp;
    cudaGetSymbolAddress((void**)&P, g_P);
    cudaGetSymbolAddress((void**)&V, g_V);
    cudaGetSymbolAddress((void**)&G, g_G);
    cudaGetSymbolAddress((void**)&Gp, g_Gpart);

    dim3 blk(256);

    // 1) P = X @ W_in^T + b_in
    gemm_nt_bias<<<dim3(EMBED / 128, M / 128), blk>>>(x, W_in, b_in, P, M, EMBED, EMBED);

    // 2) G[b,h] = scale * P_h^T P_h, K-split over seq (scale = 1/32 exactly)
    head_gram_part<<<dim3((M / SEQ) * NHEADS, GCHUNKS), blk>>>(P, Gp);
    gram_reduce<<<(32 * HDIM * HDIM + 255) / 256, blk>>>(Gp, G, 1.0f / 32.0f);

    // 3) V = P @ G per head
    apply_gram<<<dim3(M / 64, NHEADS), blk>>>(P, G, V);

    // 4) out = V @ W_out^T + b_out
    gemm_nt_bias<<<dim3((NCLS + 127) / 128, M / 128), blk>>>(V, W_out, b_out, out, M, NCLS, EMBED);
}

// round 4
// speedup vs baseline: 2.2768x; 1.9321x over previous
#include <cuda_runtime.h>
#include <cuda_bf16.h>

#define EMBED 1024
#define NHEADS 16
#define HDIM 64
#define SEQ 2048
#define NCLS 1000
#define GCHUNKS 16
#define MTOT 4096

#define BM 128
#define BN 128
#define BKE 32          // K elems per smem stage
#define NIT (EMBED / BKE)
#define PK 40           // padded row length (bf16 elems): 80B rows -> conflict-free ldmatrix
#define TSZ (BM * PK)   // elems per tensor tile in smem
#define BUFSZ (4 * TSZ) // Ah, Al, Bh, Bl
#define SMEM_BYTES (2 * BUFSZ * 2)

// ---------- scratch (__device__ globals; no allocation allowed) ----------
__device__ float g_P[MTOT * EMBED];
__device__ float g_G[32 * HDIM * HDIM];
__device__ float g_Gpart[GCHUNKS][32][HDIM * HDIM];
__device__ __nv_bfloat16 g_xh[MTOT * EMBED], g_xl[MTOT * EMBED];
__device__ __nv_bfloat16 g_wih[EMBED * EMBED], g_wil[EMBED * EMBED];
__device__ __nv_bfloat16 g_vh[MTOT * EMBED], g_vl[MTOT * EMBED];
__device__ __nv_bfloat16 g_woh[1024 * EMBED], g_wol[1024 * EMBED];

// ---------- helpers ----------
__device__ __forceinline__ unsigned smem_u32(const void* p) {
    unsigned a;
    asm("{ .reg .u64 t; cvta.to.shared.u64 t, %1; cvt.u32.u64 %0, t; }" : "=r"(a) : "l"(p));
    return a;
}
__device__ __forceinline__ void cpa16(unsigned s, const void* g) {
    asm volatile("cp.async.cg.shared.global [%0], [%1], 16;" :: "r"(s), "l"(g) : "memory");
}
#define CP_COMMIT() asm volatile("cp.async.commit_group;" ::: "memory")
#define CP_WAIT1()  asm volatile("cp.async.wait_group 1;" ::: "memory")

#define LDSM4(r0, r1, r2, r3, a) \
    asm volatile("ldmatrix.sync.aligned.m8n8.x4.shared.b16 {%0,%1,%2,%3}, [%4];" \
        : "=r"(r0), "=r"(r1), "=r"(r2), "=r"(r3) : "r"(a))

#define MMA(c, a, b0v, b1v) \
    asm volatile("mma.sync.aligned.m16n8k16.row.col.f32.bf16.bf16.f32 " \
        "{%0,%1,%2,%3},{%4,%5,%6,%7},{%8,%9},{%0,%1,%2,%3};" \
        : "+f"((c)[0]), "+f"((c)[1]), "+f"((c)[2]), "+f"((c)[3]) \
        : "r"((a)[0]), "r"((a)[1]), "r"((a)[2]), "r"((a)[3]), "r"(b0v), "r"(b1v))

__device__ __forceinline__ unsigned pack_bf(float e0, float e1) {
    unsigned r;
    asm("cvt.rn.bf16x2.f32 %0, %1, %2;" : "=r"(r) : "f"(e1), "f"(e0));
    return r;
}

// ---------- fp32 -> (hi, lo) bf16 split ----------
__global__ void cvt_split(const float4* __restrict__ X, uint2* __restrict__ H,
                          uint2* __restrict__ L, int n4) {
    int i = blockIdx.x * blockDim.x + threadIdx.x;
    if (i >= n4) return;
    float4 x = X[i];
    unsigned h01 = pack_bf(x.x, x.y), h23 = pack_bf(x.z, x.w);
    float hx = __uint_as_float(h01 << 16), hy = __uint_as_float(h01 & 0xffff0000u);
    float hz = __uint_as_float(h23 << 16), hw = __uint_as_float(h23 & 0xffff0000u);
    unsigned l01 = pack_bf(x.x - hx, x.y - hy), l23 = pack_bf(x.z - hz, x.w - hw);
    H[i] = make_uint2(h01, h23);
    L[i] = make_uint2(l01, l23);
}

__global__ void cvt_split_pad(const float4* __restrict__ X, uint2* __restrict__ H,
                              uint2* __restrict__ L, int n4, int rowsValid) {
    int i = blockIdx.x * blockDim.x + threadIdx.x;
    if (i >= n4) return;
    int row = i >> 8;
    if (row >= rowsValid) { H[i] = make_uint2(0, 0); L[i] = make_uint2(0, 0); return; }
    float4 x = X[i];
    unsigned h01 = pack_bf(x.x, x.y), h23 = pack_bf(x.z, x.w);
    float hx = __uint_as_float(h01 << 16), hy = __uint_as_float(h01 & 0xffff0000u);
    float hz = __uint_as_float(h23 << 16), hw = __uint_as_float(h23 & 0xffff0000u);
    unsigned l01 = pack_bf(x.x - hx, x.y - hy), l23 = pack_bf(x.z - hz, x.w - hw);
    H[i] = make_uint2(h01, h23);
    L[i] = make_uint2(l01, l23);
}

// ---------- bf16x3 mma.sync GEMM: C[M,N] = A @ B^T + bias ----------
// A,B hi/lo bf16, K-major, row stride EMBED. B row count padded to 128*gridDim.x.
__device__ __forceinline__ void load_stage(
    unsigned sbuf, int tid, int k0,
    const __nv_bfloat16* Ah, const __nv_bfloat16* Al,
    const __nv_bfloat16* Bh, const __nv_bfloat16* Bl,
    int m0, int n0)
{
    int row = tid >> 1;
    int q = (tid & 1) * 2;
    unsigned soff = (unsigned)(row * PK + q * 8) * 2;
    size_t ga = (size_t)(m0 + row) * EMBED + k0 + q * 8;
    size_t gb = (size_t)(n0 + row) * EMBED + k0 + q * 8;
    cpa16(sbuf + soff,                 Ah + ga);
    cpa16(sbuf + soff + 16,            Ah + ga + 8);
    cpa16(sbuf + TSZ * 2 + soff,       Al + ga);
    cpa16(sbuf + TSZ * 2 + soff + 16,  Al + ga + 8);
    cpa16(sbuf + TSZ * 4 + soff,       Bh + gb);
    cpa16(sbuf + TSZ * 4 + soff + 16,  Bh + gb + 8);
    cpa16(sbuf + TSZ * 6 + soff,       Bl + gb);
    cpa16(sbuf + TSZ * 6 + soff + 16,  Bl + gb + 8);
}

__global__ __launch_bounds__(256, 1) void gemm_mma_bf16x3(
    const __nv_bfloat16* __restrict__ Ah, const __nv_bfloat16* __restrict__ Al,
    const __nv_bfloat16* __restrict__ Bh, const __nv_bfloat16* __restrict__ Bl,
    const float* __restrict__ bias, float* __restrict__ C, int N)
{
    extern __shared__ __nv_bfloat16 sm[];
    int tid = threadIdx.x;
    int m0 = blockIdx.y * BM;
    int n0 = blockIdx.x * BN;
    unsigned sbase = smem_u32(sm);

    int wid = tid >> 5, lane = tid & 31;
    int wm = (wid & 1) * 64;    // warp M offset in tile
    int wn = (wid >> 1) * 32;   // warp N offset in tile

    float acc[4][4][4];
#pragma unroll
    for (int i = 0; i < 4; i++)
#pragma unroll
        for (int j = 0; j < 4; j++)
#pragma unroll
            for (int v = 0; v < 4; v++) acc[i][j][v] = 0.f;

    load_stage(sbase, tid, 0, Ah, Al, Bh, Bl, m0, n0);
    CP_COMMIT();

    // ldmatrix lane offsets (bytes): rows (lane&15), k-half chunk (lane>>4)*8
    unsigned a_lo = (unsigned)((wm + (lane & 15)) * PK + ((lane >> 4) << 3)) * 2;
    unsigned b_lo = (unsigned)((wn + (lane & 15)) * PK + ((lane >> 4) << 3)) * 2;

    for (int it = 0; it < NIT; it++) {
        unsigned sbuf = sbase + (unsigned)(it & 1) * (BUFSZ * 2);
        if (it + 1 < NIT)
            load_stage(sbase + (unsigned)((it + 1) & 1) * (BUFSZ * 2), tid,
                       (it + 1) * BKE, Ah, Al, Bh, Bl, m0, n0);
        CP_COMMIT();
        CP_WAIT1();
        __syncthreads();

#pragma unroll
        for (int kk = 0; kk < 2; kk++) {
            unsigned ah[4][4], al[4][4], bh[2][4], bl[2][4];
            unsigned ao = sbuf + a_lo + (unsigned)kk * 32;
            unsigned bo = sbuf + b_lo + (unsigned)kk * 32;
#pragma unroll
            for (int i = 0; i < 4; i++) {
                LDSM4(ah[i][0], ah[i][1], ah[i][2], ah[i][3], ao + (unsigned)i * (16 * PK * 2));
                LDSM4(al[i][0], al[i][1], al[i][2], al[i][3], ao + TSZ * 2 + (unsigned)i * (16 * PK * 2));
            }
#pragma unroll
            for (int L = 0; L < 2; L++) {
                LDSM4(bh[L][0], bh[L][1], bh[L][2], bh[L][3], bo + TSZ * 4 + (unsigned)L * (16 * PK * 2));
                LDSM4(bl[L][0], bl[L][1], bl[L][2], bl[L][3], bo + TSZ * 6 + (unsigned)L * (16 * PK * 2));
            }
#pragma unroll
            for (int i = 0; i < 4; i++)
#pragma unroll
                for (int j = 0; j < 4; j++) {
                    int L = j >> 1, s = j & 1;
                    MMA(acc[i][j], ah[i], bh[L][s], bh[L][s + 2]);
                    MMA(acc[i][j], ah[i], bl[L][s], bl[L][s + 2]);
                    MMA(acc[i][j], al[i], bh[L][s], bh[L][s + 2]);
                }
        }
        __syncthreads();
    }

    // epilogue: m16n8 fragment layout: rows lane>>2 (+8), cols (lane&3)*2 (+1)
    int r = lane >> 2, c2 = (lane & 3) * 2;
#pragma unroll
    for (int i = 0; i < 4; i++) {
        int m = m0 + wm + i * 16 + r;
        float* C0 = C + (size_t)m * N;
        float* C1 = C0 + (size_t)8 * N;
#pragma unroll
        for (int j = 0; j < 4; j++) {
            int n = n0 + wn + j * 8 + c2;
            if (n < N) {
                float bv = bias[n];
                C0[n] = acc[i][j][0] + bv;
                C1[n] = acc[i][j][2] + bv;
            }
            if (n + 1 < N) {
                float bv = bias[n + 1];
                C0[n + 1] = acc[i][j][1] + bv;
                C1[n + 1] = acc[i][j][3] + bv;
            }
        }
    }
}

// ---------- Gram kernels ----------
__global__ __launch_bounds__(256) void head_gram_part(
    const float* __restrict__ P, float* __restrict__ Gpart)
{
    int bh = blockIdx.x;
    int chunk = blockIdx.y;
    int b = bh >> 4;
    int h = bh & 15;
    const float* Pb = P + (size_t)b * SEQ * EMBED + h * HDIM;
    int sBeg = chunk * (SEQ / GCHUNKS);

    __shared__ float Ps[64][65];
    int tid = threadIdx.x;
    int j  = tid & 63;
    int i0 = (tid >> 6) << 4;

    float acc[16];
#pragma unroll
    for (int ii = 0; ii < 16; ii++) acc[ii] = 0.f;

    for (int s0 = sBeg; s0 < sBeg + SEQ / GCHUNKS; s0 += 64) {
        __syncthreads();
#pragma unroll
        for (int v = 0; v < 4; v++) {
            int idx = tid + v * 256;
            int rr = idx >> 4;
            int c = (idx & 15) << 2;
            float4 p4 = *(const float4*)(Pb + (size_t)(s0 + rr) * EMBED + c);
            Ps[rr][c + 0] = p4.x; Ps[rr][c + 1] = p4.y;
            Ps[rr][c + 2] = p4.z; Ps[rr][c + 3] = p4.w;
        }
        __syncthreads();
#pragma unroll 4
        for (int s = 0; s < 64; s++) {
            float bj = Ps[s][j];
#pragma unroll
            for (int ii = 0; ii < 16; ii++)
                acc[ii] += Ps[s][i0 + ii] * bj;
        }
    }

    float* Gp = Gpart + ((size_t)chunk * 32 + bh) * (HDIM * HDIM);
#pragma unroll
    for (int ii = 0; ii < 16; ii++)
        Gp[(i0 + ii) * HDIM + j] = acc[ii];
}

__global__ void gram_reduce(const float* __restrict__ Gpart,
                            float* __restrict__ G, float scale)
{
    int idx = blockIdx.x * blockDim.x + threadIdx.x;
    if (idx >= 32 * HDIM * HDIM) return;
    float s = 0.f;
#pragma unroll
    for (int c = 0; c < GCHUNKS; c++)
        s += Gpart[(size_t)c * 32 * HDIM * HDIM + idx];
    G[idx] = s * scale;
}

// V = P @ G per head; emits hi/lo bf16 split of V directly.
__global__ __launch_bounds__(256) void apply_gram(
    const float* __restrict__ P, const float* __restrict__ G,
    __nv_bfloat16* __restrict__ Vh, __nv_bfloat16* __restrict__ Vl)
{
    int h  = blockIdx.y;
    int r0 = blockIdx.x * 64;
    int b  = r0 / SEQ;
    const float* Gh = G + (size_t)(b * NHEADS + h) * HDIM * HDIM;

    __shared__ float Gs[64][65];
    __shared__ float Ps[64][65];
    int tid = threadIdx.x;

#pragma unroll
    for (int v = 0; v < 4; v++) {
        int idx = tid + v * 256;
        int rr = idx >> 4;
        int c = (idx & 15) << 2;
        float4 g4 = *(const float4*)(Gh + rr * HDIM + c);
        Gs[rr][c + 0] = g4.x; Gs[rr][c + 1] = g4.y;
        Gs[rr][c + 2] = g4.z; Gs[rr][c + 3] = g4.w;
        float4 p4 = *(const float4*)(P + (size_t)(r0 + rr) * EMBED + h * HDIM + c);
        Ps[rr][c + 0] = p4.x; Ps[rr][c + 1] = p4.y;
        Ps[rr][c + 2] = p4.z; Ps[rr][c + 3] = p4.w;
    }
    __syncthreads();

    int j  = tid & 63;
    int i0 = (tid >> 6) << 4;
    float acc[16];
#pragma unroll
    for (int ii = 0; ii < 16; ii++) acc[ii] = 0.f;

#pragma unroll 4
    for (int k = 0; k < 64; k++) {
        float g = Gs[k][j];
#pragma unroll
        for (int ii = 0; ii < 16; ii++)
            acc[ii] += Ps[i0 + ii][k] * g;
    }

#pragma unroll
    for (int ii = 0; ii < 16; ii++) {
        size_t o = (size_t)(r0 + i0 + ii) * EMBED + h * HDIM + j;
        float v = acc[ii];
        __nv_bfloat16 hi = __float2bfloat16(v);
        Vh[o] = hi;
        Vl[o] = __float2bfloat16(v - __bfloat162float(hi));
    }
}

// ---------- launch ----------
extern "C" void kernel_launch(void* const* d_in, const int* in_sizes, int n_in,
                              void* d_out, int out_size)
{
    const float* x     = (const float*)d_in[0];
    const float* W_in  = (const float*)d_in[1];
    const float* b_in  = (const float*)d_in[2];
    const float* W_out = (const float*)d_in[3];
    const float* b_out = (const float*)d_in[4];
    float* out = (float*)d_out;

    int M = in_sizes[0] / EMBED;   // 4096

    float *P, *G, *Gp;
    cudaGetSymbolAddress((void**)&P, g_P);
    cudaGetSymbolAddress((void**)&G, g_G);
    cudaGetSymbolAddress((void**)&Gp, g_Gpart);
    __nv_bfloat16 *xh, *xl, *wih, *wil, *vh, *vl, *woh, *wol;
    cudaGetSymbolAddress((void**)&xh, g_xh);
    cudaGetSymbolAddress((void**)&xl, g_xl);
    cudaGetSymbolAddress((void**)&wih, g_wih);
    cudaGetSymbolAddress((void**)&wil, g_wil);
    cudaGetSymbolAddress((void**)&vh, g_vh);
    cudaGetSymbolAddress((void**)&vl, g_vl);
    cudaGetSymbolAddress((void**)&woh, g_woh);
    cudaGetSymbolAddress((void**)&wol, g_wol);

    cudaFuncSetAttribute(gemm_mma_bf16x3, cudaFuncAttributeMaxDynamicSharedMemorySize, SMEM_BYTES);

    dim3 blk(256);

    // split inputs to hi/lo bf16
    cvt_split<<<(M * EMBED / 4) / 256, blk>>>((const float4*)x, (uint2*)xh, (uint2*)xl, M * EMBED / 4);
    cvt_split<<<(EMBED * EMBED / 4) / 256, blk>>>((const float4*)W_in, (uint2*)wih, (uint2*)wil, EMBED * EMBED / 4);
    cvt_split_pad<<<(1024 * EMBED / 4) / 256, blk>>>((const float4*)W_out, (uint2*)woh, (uint2*)wol,
                                                     1024 * EMBED / 4, NCLS);

    // 1) P = X @ W_in^T + b_in   (tensor cores via mma.sync, bf16x3)
    gemm_mma_bf16x3<<<dim3(EMBED / BN, M / BM), blk, SMEM_BYTES>>>(xh, xl, wih, wil, b_in, P, EMBED);

    // 2) G = scale * P_h^T P_h   (K-split, deterministic reduce; scale = 1/32)
    head_gram_part<<<dim3((M / SEQ) * NHEADS, GCHUNKS), blk>>>(P, Gp);
    gram_reduce<<<(32 * HDIM * HDIM + 255) / 256, blk>>>(Gp, G, 1.0f / 32.0f);

    // 3) V = P @ G per head (emits hi/lo bf16 split directly)
    apply_gram<<<dim3(M / 64, NHEADS), blk>>>(P, G, vh, vl);

    // 4) out = V @ W_out^T + b_out
    gemm_mma_bf16x3<<<dim3(1024 / BN, M / BM), blk, SMEM_BYTES>>>(vh, vl, woh, wol, b_out, out, NCLS);
}